// round 2
// baseline (speedup 1.0000x reference)
#include <cuda_runtime.h>
#include <mma.h>
#include <math.h>

using namespace nvcuda;

#define T 2048
#define H 2048
#define QKV_N 3072
#define NH 32
#define NKV 8
#define QM 4
#define HD 64
#define SW 128
#define QT 32
#define MAXK (SW + QT)   // 160 keys max per query tile

// GEMM tiling
#define BM 128
#define BN 128
#define BK 32
#define AP 36    // As leading dim (pad), 144B rows (16B-aligned)
#define BP 132   // Bs leading dim (pad)
#define SP 36    // epilogue stage leading dim
#define GEMM_SMEM 73728  // 8 warps * 64 * 36 * 4B (covers As+Bs 35328B too)

// ---------------- scratch (device globals; no allocation allowed) ----------
__device__ float g_normed[(size_t)T * H];
__device__ float g_qkv[(size_t)T * QKV_N];
__device__ float g_attn[(size_t)T * H];

// ---------------- RMSNorm ---------------------------------------------------
__global__ __launch_bounds__(256) void rmsnorm_kernel(const float* __restrict__ x,
                                                      const float* __restrict__ scale) {
    int row = blockIdx.x;
    const float* xr = x + (size_t)row * H;
    float ss = 0.f;
    for (int i = threadIdx.x; i < H; i += 256) { float v = xr[i]; ss += v * v; }
    for (int o = 16; o > 0; o >>= 1) ss += __shfl_xor_sync(0xffffffffu, ss, o);
    __shared__ float red[8];
    int wid = threadIdx.x >> 5, lane = threadIdx.x & 31;
    if (lane == 0) red[wid] = ss;
    __syncthreads();
    __shared__ float s_inv;
    if (threadIdx.x == 0) {
        float t = 0.f;
        #pragma unroll
        for (int i = 0; i < 8; i++) t += red[i];
        s_inv = rsqrtf(t * (1.0f / (float)H) + 1e-5f);
    }
    __syncthreads();
    float inv = s_inv;
    for (int i = threadIdx.x; i < H; i += 256)
        g_normed[(size_t)row * H + i] = xr[i] * inv * scale[i];
}

// ---------------- tf32 WMMA GEMM: C = A[M,K] @ B[K,N] + bias (+resid) ------
// 128x128 block tile, BK=32, 8 warps (2x4), 64x32 warp tile, m16n16k8 tf32.
__global__ __launch_bounds__(256) void gemm_tf32_kernel(const float* __restrict__ A,
                                                        const float* __restrict__ B,
                                                        const float* __restrict__ bias,
                                                        const float* __restrict__ resid,
                                                        float* __restrict__ C,
                                                        int N, int K) {
    extern __shared__ float sm[];
    float* As = sm;               // [BM][AP]
    float* Bs = sm + BM * AP;     // [BK][BP]

    int tid = threadIdx.x;
    int warpId = tid >> 5, lane = tid & 31;
    int wm = warpId & 1;          // 0..1  (64-row slab)
    int wn = warpId >> 1;         // 0..3  (32-col slab)
    int bm = blockIdx.y * BM, bn = blockIdx.x * BN;

    wmma::fragment<wmma::accumulator, 16, 16, 8, float> acc[4][2];
    #pragma unroll
    for (int i = 0; i < 4; i++)
        #pragma unroll
        for (int j = 0; j < 2; j++)
            wmma::fill_fragment(acc[i][j], 0.0f);

    for (int k0 = 0; k0 < K; k0 += BK) {
        // load A tile [BM][BK]: 1024 float4, 4 per thread
        #pragma unroll
        for (int i = 0; i < 4; i++) {
            int id = tid + i * 256;
            int r = id >> 3, c = (id & 7) << 2;
            *(float4*)&As[r * AP + c] = *(const float4*)&A[(size_t)(bm + r) * K + k0 + c];
        }
        // load B tile [BK][BN]: 1024 float4, 4 per thread
        #pragma unroll
        for (int i = 0; i < 4; i++) {
            int id = tid + i * 256;
            int r = id >> 5, c = (id & 31) << 2;
            *(float4*)&Bs[r * BP + c] = *(const float4*)&B[(size_t)(k0 + r) * N + bn + c];
        }
        __syncthreads();

        #pragma unroll
        for (int kk = 0; kk < BK; kk += 8) {
            wmma::fragment<wmma::matrix_a, 16, 16, 8, wmma::precision::tf32, wmma::row_major> af[4];
            wmma::fragment<wmma::matrix_b, 16, 16, 8, wmma::precision::tf32, wmma::row_major> bf[2];
            #pragma unroll
            for (int i = 0; i < 4; i++) {
                wmma::load_matrix_sync(af[i], &As[(wm * 64 + i * 16) * AP + kk], AP);
                #pragma unroll
                for (int t = 0; t < af[i].num_elements; t++)
                    af[i].x[t] = wmma::__float_to_tf32(af[i].x[t]);
            }
            #pragma unroll
            for (int j = 0; j < 2; j++) {
                wmma::load_matrix_sync(bf[j], &Bs[kk * BP + wn * 32 + j * 16], BP);
                #pragma unroll
                for (int t = 0; t < bf[j].num_elements; t++)
                    bf[j].x[t] = wmma::__float_to_tf32(bf[j].x[t]);
            }
            #pragma unroll
            for (int i = 0; i < 4; i++)
                #pragma unroll
                for (int j = 0; j < 2; j++)
                    wmma::mma_sync(acc[i][j], af[i], bf[j], acc[i][j]);
        }
        __syncthreads();
    }

    // epilogue: stage per-warp 64x32 in smem, then add bias (+resid) and write
    float* stg = sm + (size_t)warpId * 64 * SP;
    #pragma unroll
    for (int i = 0; i < 4; i++)
        #pragma unroll
        for (int j = 0; j < 2; j++)
            wmma::store_matrix_sync(&stg[(i * 16) * SP + j * 16], acc[i][j], SP, wmma::mem_row_major);
    __syncwarp();

    int gc = bn + wn * 32 + lane;
    float bv = bias[gc];
    #pragma unroll 4
    for (int r = 0; r < 64; r++) {
        int gr = bm + wm * 64 + r;
        float v = stg[r * SP + lane] + bv;
        if (resid) v += resid[(size_t)gr * N + gc];
        C[(size_t)gr * N + gc] = v;
    }
}

// ---------------- RoPE (split-half rotation), in place on g_qkv -------------
__global__ __launch_bounds__(256) void rope_kernel(const float* __restrict__ cosb,
                                                   const float* __restrict__ sinb) {
    int idx = blockIdx.x * 256 + threadIdx.x;
    if (idx >= T * 40 * 32) return;
    int i = idx & 31;
    int h = (idx >> 5) % 40;
    int t = idx / (40 * 32);
    int col = (h < 32) ? (h * HD) : (H + (h - 32) * HD);
    float* p = g_qkv + (size_t)t * QKV_N + col;
    float c = cosb[t * 32 + i], s = sinb[t * 32 + i];
    float x1 = p[i], x2 = p[i + 32];
    p[i] = x1 * c - x2 * s;
    p[i + 32] = x2 * c + x1 * s;
}

// ---------------- windowed GQA attention with sinks -------------------------
__global__ __launch_bounds__(128) void attn_kernel(const float* __restrict__ sinks) {
    extern __shared__ float sh[];
    float* Ksh = sh;
    float* Vsh = sh + MAXK * HD;
    int nkv = blockIdx.y;
    int q0 = blockIdx.x * QT;
    int ks = q0 - SW; if (ks < 0) ks = 0;
    int nk = q0 + QT - ks;
    const float* kbase = g_qkv + H + nkv * HD;
    const float* vbase = g_qkv + H + NKV * HD + nkv * HD;
    for (int idx = threadIdx.x; idx < nk * 16; idx += 128) {
        int r = idx >> 4, c4 = (idx & 15) << 2;
        *(float4*)(Ksh + r * HD + c4) = *(const float4*)(kbase + (size_t)(ks + r) * QKV_N + c4);
        *(float4*)(Vsh + r * HD + c4) = *(const float4*)(vbase + (size_t)(ks + r) * QKV_N + c4);
    }
    __syncthreads();

    int qm = threadIdx.x >> 5;
    int q = q0 + (threadIdx.x & 31);
    int hh = nkv * QM + qm;

    float4 qreg[16];
    const float4* qp = (const float4*)(g_qkv + (size_t)q * QKV_N + hh * HD);
    const float smscale = 0.125f;
    #pragma unroll
    for (int i = 0; i < 16; i++) {
        float4 v = qp[i];
        v.x *= smscale; v.y *= smscale; v.z *= smscale; v.w *= smscale;
        qreg[i] = v;
    }
    float4 acc[16];
    #pragma unroll
    for (int i = 0; i < 16; i++) acc[i] = make_float4(0.f, 0.f, 0.f, 0.f);
    float l = 0.f;

    for (int kk = 0; kk < nk; kk++) {
        int kp = ks + kk;
        const float4* kr = (const float4*)(Ksh + kk * HD);
        float s = 0.f;
        #pragma unroll
        for (int i = 0; i < 16; i++) {
            float4 kv = kr[i];
            s += qreg[i].x * kv.x + qreg[i].y * kv.y + qreg[i].z * kv.z + qreg[i].w * kv.w;
        }
        bool valid = (kp <= q) && (q - kp <= SW);
        float p = valid ? __expf(s) : 0.f;
        l += p;
        const float4* vr = (const float4*)(Vsh + kk * HD);
        #pragma unroll
        for (int i = 0; i < 16; i++) {
            float4 vv = vr[i];
            acc[i].x += p * vv.x; acc[i].y += p * vv.y;
            acc[i].z += p * vv.z; acc[i].w += p * vv.w;
        }
    }
    float inv = 1.f / (l + __expf(sinks[hh]));
    float4* outp = (float4*)(g_attn + (size_t)q * H + hh * HD);
    #pragma unroll
    for (int i = 0; i < 16; i++) {
        float4 v = acc[i];
        v.x *= inv; v.y *= inv; v.z *= inv; v.w *= inv;
        outp[i] = v;
    }
}

// ---------------- launch -----------------------------------------------------
extern "C" void kernel_launch(void* const* d_in, const int* in_sizes, int n_in,
                              void* d_out, int out_size) {
    const float* x          = (const float*)d_in[0];
    const float* scale      = (const float*)d_in[1];
    const float* sinks      = (const float*)d_in[2];
    const float* qkv_kernel = (const float*)d_in[3];
    const float* qkv_bias   = (const float*)d_in[4];
    const float* out_kernel = (const float*)d_in[5];
    const float* out_bias   = (const float*)d_in[6];
    const float* cosb       = (const float*)d_in[7];
    const float* sinb       = (const float*)d_in[8];
    float* out = (float*)d_out;

    float *pn, *pq, *pa;
    cudaGetSymbolAddress((void**)&pn, g_normed);
    cudaGetSymbolAddress((void**)&pq, g_qkv);
    cudaGetSymbolAddress((void**)&pa, g_attn);

    int attn_smem = MAXK * HD * 2 * (int)sizeof(float);  // 81920 B
    cudaFuncSetAttribute(attn_kernel, cudaFuncAttributeMaxDynamicSharedMemorySize, attn_smem);
    cudaFuncSetAttribute(gemm_tf32_kernel, cudaFuncAttributeMaxDynamicSharedMemorySize, GEMM_SMEM);

    rmsnorm_kernel<<<T, 256>>>(x, scale);
    gemm_tf32_kernel<<<dim3(QKV_N / BN, T / BM), 256, GEMM_SMEM>>>(pn, qkv_kernel, qkv_bias, nullptr, pq, QKV_N, H);
    rope_kernel<<<(T * 40 * 32 + 255) / 256, 256>>>(cosb, sinb);
    attn_kernel<<<dim3(T / QT, NKV), 128, attn_smem>>>(sinks);
    gemm_tf32_kernel<<<dim3(H / BN, T / BM), 256, GEMM_SMEM>>>(pa, out_kernel, out_bias, x, out, H, H);
}

// round 5
// speedup vs baseline: 4.2807x; 4.2807x over previous
#include <cuda_runtime.h>
#include <cuda_bf16.h>
#include <cstdint>
#include <math.h>

#define T 2048
#define H 2048
#define QKV_N 3072
#define NH 32
#define NKV 8
#define QM 4
#define HD 64
#define SW 128
#define QT 32
#define MAXK (SW + QT)   // 160 keys max per query tile

// ---- GEMM tiling (mma.sync bf16) ----
#define BM 128
#define BN 128
#define BK 32
#define RS 80                       // padded smem row stride in bytes (64B data + 16B pad)
#define STAGE_A (128 * RS)          // 10240 B
#define STAGE (2 * STAGE_A)         // 20480 B
#define NSTAGE 4
#define GEMM_SMEM (NSTAGE * STAGE)  // 81920 B

// ---------------- scratch (device globals; no allocation allowed) ----------
__device__ __nv_bfloat16 g_act[(size_t)T * H];          // rmsnorm output (bf16)
__device__ float        g_qkv[(size_t)T * QKV_N];       // qkv output (fp32)
__device__ __nv_bfloat16 g_attn[(size_t)T * H];         // attention output (bf16)
__device__ __nv_bfloat16 g_qkvw_t[(size_t)QKV_N * H];   // qkv weight [N,K] bf16
__device__ __nv_bfloat16 g_outw_t[(size_t)H * H];       // out weight [N,K] bf16

// ---------------- helpers ----------------------------------------------
__device__ __forceinline__ uint32_t smem_u32(const void* p) {
    uint32_t a;
    asm("{ .reg .u64 t; cvta.to.shared.u64 t, %1; cvt.u32.u64 %0, t; }" : "=r"(a) : "l"(p));
    return a;
}
__device__ __forceinline__ void cp_async16(uint32_t saddr, const void* gaddr) {
    asm volatile("cp.async.cg.shared.global [%0], [%1], 16;" :: "r"(saddr), "l"(gaddr));
}
__device__ __forceinline__ void ldsm4(uint32_t* r, uint32_t a) {
    asm volatile("ldmatrix.sync.aligned.m8n8.x4.shared.b16 {%0,%1,%2,%3}, [%4];"
        : "=r"(r[0]), "=r"(r[1]), "=r"(r[2]), "=r"(r[3]) : "r"(a));
}
__device__ __forceinline__ void mma16816(float* c, const uint32_t* a, const uint32_t* b) {
    asm volatile("mma.sync.aligned.m16n8k16.row.col.f32.bf16.bf16.f32 "
        "{%0,%1,%2,%3}, {%4,%5,%6,%7}, {%8,%9}, {%0,%1,%2,%3};"
        : "+f"(c[0]), "+f"(c[1]), "+f"(c[2]), "+f"(c[3])
        : "r"(a[0]), "r"(a[1]), "r"(a[2]), "r"(a[3]), "r"(b[0]), "r"(b[1]));
}

// ---------------- RMSNorm -> bf16 -------------------------------------------
__global__ __launch_bounds__(256) void rmsnorm_kernel(const float* __restrict__ x,
                                                      const float* __restrict__ scale) {
    int row = blockIdx.x;
    const float* xr = x + (size_t)row * H;
    float ss = 0.f;
    for (int i = threadIdx.x; i < H; i += 256) { float v = xr[i]; ss += v * v; }
    for (int o = 16; o > 0; o >>= 1) ss += __shfl_xor_sync(0xffffffffu, ss, o);
    __shared__ float red[8];
    int wid = threadIdx.x >> 5, lane = threadIdx.x & 31;
    if (lane == 0) red[wid] = ss;
    __syncthreads();
    __shared__ float s_inv;
    if (threadIdx.x == 0) {
        float t = 0.f;
        #pragma unroll
        for (int i = 0; i < 8; i++) t += red[i];
        s_inv = rsqrtf(t * (1.0f / (float)H) + 1e-5f);
    }
    __syncthreads();
    float inv = s_inv;
    for (int i = threadIdx.x; i < H; i += 256)
        g_act[(size_t)row * H + i] = __float2bfloat16(xr[i] * inv * scale[i]);
}

// ---------------- weight transpose + bf16 convert: [K,N] f32 -> [N,K] bf16 --
__global__ __launch_bounds__(256) void transpose_bf16_kernel(const float* __restrict__ S,
                                                             __nv_bfloat16* __restrict__ D,
                                                             int K, int N) {
    __shared__ float t[32][33];
    int n0 = blockIdx.x * 32, k0 = blockIdx.y * 32;
    int tx = threadIdx.x & 31, ty = threadIdx.x >> 5;
    #pragma unroll
    for (int i = 0; i < 32; i += 8)
        t[ty + i][tx] = S[(size_t)(k0 + ty + i) * N + n0 + tx];
    __syncthreads();
    #pragma unroll
    for (int i = 0; i < 32; i += 8)
        D[(size_t)(n0 + ty + i) * K + k0 + tx] = __float2bfloat16(t[tx][ty + i]);
}

// ---------------- bf16 mma.sync GEMM: C = A[M,K] @ Bt[N,K]^T + bias (+resid)
// 128x128x32 CTA tile, 8 warps (2x4), 64x32 warp tile, 4-stage cp.async.
__global__ __launch_bounds__(256) void gemm_tc_kernel(const __nv_bfloat16* __restrict__ A,
                                                      const __nv_bfloat16* __restrict__ Bt,
                                                      const float* __restrict__ bias,
                                                      const float* __restrict__ resid,
                                                      float* __restrict__ C,
                                                      int N, int K) {
    extern __shared__ char smem[];
    uint32_t sbase = smem_u32(smem);

    int tid = threadIdx.x;
    int wid = tid >> 5, lane = tid & 31;
    int wm = wid & 1;          // 0..1 : 64-row slab
    int wn = wid >> 1;         // 0..3 : 32-col slab
    int bm = blockIdx.y * BM, bn = blockIdx.x * BN;

    float acc[4][4][4];
    #pragma unroll
    for (int i = 0; i < 4; i++)
        #pragma unroll
        for (int j = 0; j < 4; j++)
            #pragma unroll
            for (int e = 0; e < 4; e++) acc[i][j][e] = 0.f;

    const int nk = K / BK;

    // stage loader: A[128][32] + B[128][32] bf16, padded rows
    auto load_stage = [&](int it) {
        uint32_t sb = sbase + (it & (NSTAGE - 1)) * STAGE;
        const __nv_bfloat16* Ag = A + (size_t)bm * K + it * BK;
        const __nv_bfloat16* Bg = Bt + (size_t)bn * K + it * BK;
        #pragma unroll
        for (int i = 0; i < 2; i++) {
            int c = tid + i * 256;
            int row = c >> 2, h = c & 3;
            cp_async16(sb + row * RS + h * 16, Ag + (size_t)row * K + h * 8);
        }
        #pragma unroll
        for (int i = 0; i < 2; i++) {
            int c = tid + i * 256;
            int row = c >> 2, h = c & 3;
            cp_async16(sb + STAGE_A + row * RS + h * 16, Bg + (size_t)row * K + h * 8);
        }
        asm volatile("cp.async.commit_group;" ::: "memory");
    };

    load_stage(0);
    load_stage(1);
    load_stage(2);

    // per-lane ldmatrix offsets
    uint32_t aoff = (uint32_t)(lane & 15) * RS + (uint32_t)(lane >> 4) * 16;
    uint32_t boff = (uint32_t)(wn * 32 + ((lane >> 4) << 3) + (lane & 7)) * RS
                  + (uint32_t)((lane >> 3) & 1) * 16;

    for (int it = 0; it < nk; it++) {
        asm volatile("cp.async.wait_group 2;" ::: "memory");
        __syncthreads();
        uint32_t sb = sbase + (it & (NSTAGE - 1)) * STAGE;
        uint32_t aBase = sb + (uint32_t)(wm * 64) * RS + aoff;
        uint32_t bBase = sb + STAGE_A + boff;
        #pragma unroll
        for (int ks = 0; ks < 2; ks++) {
            uint32_t a[4][4], b[2][4];
            #pragma unroll
            for (int mi = 0; mi < 4; mi++)
                ldsm4(a[mi], aBase + (uint32_t)(mi * 16) * RS + ks * 32);
            #pragma unroll
            for (int ng = 0; ng < 2; ng++)
                ldsm4(b[ng], bBase + (uint32_t)(ng * 16) * RS + ks * 32);
            #pragma unroll
            for (int mi = 0; mi < 4; mi++) {
                mma16816(acc[mi][0], a[mi], &b[0][0]);
                mma16816(acc[mi][1], a[mi], &b[0][2]);
                mma16816(acc[mi][2], a[mi], &b[1][0]);
                mma16816(acc[mi][3], a[mi], &b[1][2]);
            }
        }
        if (it + 3 < nk) load_stage(it + 3);
        else asm volatile("cp.async.commit_group;" ::: "memory");
    }

    // epilogue: fragment layout direct to global
    int rq = lane >> 2, cq = (lane & 3) * 2;
    #pragma unroll
    for (int mi = 0; mi < 4; mi++) {
        int r0 = bm + wm * 64 + mi * 16 + rq;
        #pragma unroll
        for (int half = 0; half < 2; half++) {
            int r = r0 + half * 8;
            float* crow = C + (size_t)r * N;
            const float* rrow = resid ? resid + (size_t)r * N : (const float*)0;
            #pragma unroll
            for (int nj = 0; nj < 4; nj++) {
                int c = bn + wn * 32 + nj * 8 + cq;
                float2 v;
                v.x = acc[mi][nj][half * 2 + 0] + bias[c];
                v.y = acc[mi][nj][half * 2 + 1] + bias[c + 1];
                if (rrow) { v.x += rrow[c]; v.y += rrow[c + 1]; }
                *(float2*)&crow[c] = v;
            }
        }
    }
}

// ---------------- RoPE (split-half rotation), in place on g_qkv -------------
__global__ __launch_bounds__(256) void rope_kernel(const float* __restrict__ cosb,
                                                   const float* __restrict__ sinb) {
    int idx = blockIdx.x * 256 + threadIdx.x;
    if (idx >= T * 40 * 32) return;
    int i = idx & 31;
    int h = (idx >> 5) % 40;
    int t = idx / (40 * 32);
    int col = (h < 32) ? (h * HD) : (H + (h - 32) * HD);
    float* p = g_qkv + (size_t)t * QKV_N + col;
    float c = cosb[t * 32 + i], s = sinb[t * 32 + i];
    float x1 = p[i], x2 = p[i + 32];
    p[i] = x1 * c - x2 * s;
    p[i + 32] = x2 * c + x1 * s;
}

// ---------------- windowed GQA attention with sinks -> bf16 -----------------
// K in smem fp32 (40KB), V in smem bf16 (20KB) => 3 CTAs/SM.
__global__ __launch_bounds__(128, 3) void attn_kernel(const float* __restrict__ sinks) {
    extern __shared__ char sh[];
    float* Ksh = (float*)sh;                                  // [MAXK][64] f32
    __nv_bfloat162* Vsh = (__nv_bfloat162*)(sh + MAXK * HD * 4); // [MAXK][32] bf162
    int nkv = blockIdx.y;
    int q0 = blockIdx.x * QT;
    int ks = q0 - SW; if (ks < 0) ks = 0;
    int nk = q0 + QT - ks;
    const float* kbase = g_qkv + H + nkv * HD;
    const float* vbase = g_qkv + H + NKV * HD + nkv * HD;
    for (int idx = threadIdx.x; idx < nk * 16; idx += 128) {
        int r = idx >> 4, c4 = (idx & 15) << 2;
        *(float4*)(Ksh + r * HD + c4) = *(const float4*)(kbase + (size_t)(ks + r) * QKV_N + c4);
        float4 v = *(const float4*)(vbase + (size_t)(ks + r) * QKV_N + c4);
        Vsh[r * 32 + (c4 >> 1)]     = __floats2bfloat162_rn(v.x, v.y);
        Vsh[r * 32 + (c4 >> 1) + 1] = __floats2bfloat162_rn(v.z, v.w);
    }
    __syncthreads();

    int qm = threadIdx.x >> 5;
    int q = q0 + (threadIdx.x & 31);
    int hh = nkv * QM + qm;

    float4 qreg[16];
    const float4* qp = (const float4*)(g_qkv + (size_t)q * QKV_N + hh * HD);
    const float smscale = 0.125f;
    #pragma unroll
    for (int i = 0; i < 16; i++) {
        float4 v = qp[i];
        v.x *= smscale; v.y *= smscale; v.z *= smscale; v.w *= smscale;
        qreg[i] = v;
    }
    float4 acc[16];
    #pragma unroll
    for (int i = 0; i < 16; i++) acc[i] = make_float4(0.f, 0.f, 0.f, 0.f);
    float l = 0.f;

    for (int kk = 0; kk < nk; kk++) {
        int kp = ks + kk;
        const float4* kr = (const float4*)(Ksh + kk * HD);
        float s0 = 0.f, s1 = 0.f, s2 = 0.f, s3 = 0.f;
        #pragma unroll
        for (int i = 0; i < 16; i += 4) {
            float4 a = kr[i], b = kr[i + 1], c = kr[i + 2], d = kr[i + 3];
            s0 += qreg[i].x * a.x + qreg[i].y * a.y + qreg[i].z * a.z + qreg[i].w * a.w;
            s1 += qreg[i+1].x * b.x + qreg[i+1].y * b.y + qreg[i+1].z * b.z + qreg[i+1].w * b.w;
            s2 += qreg[i+2].x * c.x + qreg[i+2].y * c.y + qreg[i+2].z * c.z + qreg[i+2].w * c.w;
            s3 += qreg[i+3].x * d.x + qreg[i+3].y * d.y + qreg[i+3].z * d.z + qreg[i+3].w * d.w;
        }
        float s = (s0 + s1) + (s2 + s3);
        bool valid = (kp <= q) && (q - kp <= SW);
        float p = valid ? __expf(s) : 0.f;
        l += p;
        const __nv_bfloat162* vr = Vsh + kk * 32;
        #pragma unroll
        for (int i = 0; i < 16; i++) {
            float2 v0 = __bfloat1622float2(vr[2 * i]);
            float2 v1 = __bfloat1622float2(vr[2 * i + 1]);
            acc[i].x += p * v0.x; acc[i].y += p * v0.y;
            acc[i].z += p * v1.x; acc[i].w += p * v1.y;
        }
    }
    float inv = 1.f / (l + __expf(sinks[hh]));
    __nv_bfloat162* outp = (__nv_bfloat162*)(g_attn + (size_t)q * H + hh * HD);
    #pragma unroll
    for (int i = 0; i < 16; i++) {
        outp[2 * i]     = __floats2bfloat162_rn(acc[i].x * inv, acc[i].y * inv);
        outp[2 * i + 1] = __floats2bfloat162_rn(acc[i].z * inv, acc[i].w * inv);
    }
}

// ---------------- launch -----------------------------------------------------
extern "C" void kernel_launch(void* const* d_in, const int* in_sizes, int n_in,
                              void* d_out, int out_size) {
    const float* x          = (const float*)d_in[0];
    const float* scale      = (const float*)d_in[1];
    const float* sinks      = (const float*)d_in[2];
    const float* qkv_kernel = (const float*)d_in[3];
    const float* qkv_bias   = (const float*)d_in[4];
    const float* out_kernel = (const float*)d_in[5];
    const float* out_bias   = (const float*)d_in[6];
    const float* cosb       = (const float*)d_in[7];
    const float* sinb       = (const float*)d_in[8];
    float* out = (float*)d_out;

    __nv_bfloat16 *pact, *pattn, *pqw, *pow;
    float* pq;
    cudaGetSymbolAddress((void**)&pact, g_act);
    cudaGetSymbolAddress((void**)&pq, g_qkv);
    cudaGetSymbolAddress((void**)&pattn, g_attn);
    cudaGetSymbolAddress((void**)&pqw, g_qkvw_t);
    cudaGetSymbolAddress((void**)&pow, g_outw_t);

    int attn_smem = MAXK * HD * 4 + MAXK * HD * 2;   // 61440
    cudaFuncSetAttribute(attn_kernel, cudaFuncAttributeMaxDynamicSharedMemorySize, attn_smem);
    cudaFuncSetAttribute(gemm_tc_kernel, cudaFuncAttributeMaxDynamicSharedMemorySize, GEMM_SMEM);

    rmsnorm_kernel<<<T, 256>>>(x, scale);
    transpose_bf16_kernel<<<dim3(QKV_N / 32, H / 32), 256>>>(qkv_kernel, pqw, H, QKV_N);
    transpose_bf16_kernel<<<dim3(H / 32, H / 32), 256>>>(out_kernel, pow, H, H);
    gemm_tc_kernel<<<dim3(QKV_N / BN, T / BM), 256, GEMM_SMEM>>>(pact, pqw, qkv_bias, nullptr, pq, QKV_N, H);
    rope_kernel<<<(T * 40 * 32 + 255) / 256, 256>>>(cosb, sinb);
    attn_kernel<<<dim3(T / QT, NKV), 128, attn_smem>>>(sinks);
    gemm_tc_kernel<<<dim3(H / BN, T / BM), 256, GEMM_SMEM>>>(pattn, pow, out_bias, x, out, H, H);
}

// round 6
// speedup vs baseline: 5.6371x; 1.3169x over previous
#include <cuda_runtime.h>
#include <cuda_bf16.h>
#include <cstdint>
#include <math.h>

#define T 2048
#define H 2048
#define QKV_N 3072
#define NH 32
#define NKV 8
#define QM 4
#define HD 64
#define SW 128
#define QT 32
#define MAXK (SW + QT)   // 160 keys max per query tile

// ---- GEMM tiling (mma.sync bf16) ----
#define BM 128
#define BN 128
#define BK 32
#define RS 80                       // padded smem row stride in bytes
#define STAGE_A (128 * RS)          // 10240 B
#define STAGE (2 * STAGE_A)         // 20480 B
#define NSTAGE 4
#define GEMM_SMEM (NSTAGE * STAGE)  // 81920 B

// ---- attention smem (floats) ----
#define QSTR 68
#define KSTR 68
#define VSTR 72
#define PSTR 36
#define ATT_Q_FL (4 * 32 * QSTR)          // 8704
#define ATT_K_FL (MAXK * KSTR)            // 10880
#define ATT_V_FL (MAXK * VSTR)            // 11520
#define ATT_P_FL (4 * 32 * PSTR)          // 4608
#define ATT_SMEM ((ATT_Q_FL + ATT_K_FL + ATT_V_FL + ATT_P_FL) * 4)  // 142848 B

// ---------------- scratch (device globals; no allocation allowed) ----------
__device__ __nv_bfloat16 g_act[(size_t)T * H];          // rmsnorm output (bf16)
__device__ float        g_qkv[(size_t)T * QKV_N];       // qkv output (fp32)
__device__ __nv_bfloat16 g_attn[(size_t)T * H];         // attention output (bf16)
__device__ __nv_bfloat16 g_qkvw_t[(size_t)QKV_N * H];   // qkv weight [N,K] bf16
__device__ __nv_bfloat16 g_outw_t[(size_t)H * H];       // out weight [N,K] bf16

// ---------------- helpers ----------------------------------------------
__device__ __forceinline__ uint32_t smem_u32(const void* p) {
    uint32_t a;
    asm("{ .reg .u64 t; cvta.to.shared.u64 t, %1; cvt.u32.u64 %0, t; }" : "=r"(a) : "l"(p));
    return a;
}
__device__ __forceinline__ void cp_async16(uint32_t saddr, const void* gaddr) {
    asm volatile("cp.async.cg.shared.global [%0], [%1], 16;" :: "r"(saddr), "l"(gaddr));
}
__device__ __forceinline__ void ldsm4(uint32_t* r, uint32_t a) {
    asm volatile("ldmatrix.sync.aligned.m8n8.x4.shared.b16 {%0,%1,%2,%3}, [%4];"
        : "=r"(r[0]), "=r"(r[1]), "=r"(r[2]), "=r"(r[3]) : "r"(a));
}
__device__ __forceinline__ void mma16816(float* c, const uint32_t* a, const uint32_t* b) {
    asm volatile("mma.sync.aligned.m16n8k16.row.col.f32.bf16.bf16.f32 "
        "{%0,%1,%2,%3}, {%4,%5,%6,%7}, {%8,%9}, {%0,%1,%2,%3};"
        : "+f"(c[0]), "+f"(c[1]), "+f"(c[2]), "+f"(c[3])
        : "r"(a[0]), "r"(a[1]), "r"(a[2]), "r"(a[3]), "r"(b[0]), "r"(b[1]));
}
__device__ __forceinline__ void mma_tf32(float* c, const uint32_t* a, const uint32_t* b) {
    asm volatile("mma.sync.aligned.m16n8k8.row.col.f32.tf32.tf32.f32 "
        "{%0,%1,%2,%3}, {%4,%5,%6,%7}, {%8,%9}, {%0,%1,%2,%3};"
        : "+f"(c[0]), "+f"(c[1]), "+f"(c[2]), "+f"(c[3])
        : "r"(a[0]), "r"(a[1]), "r"(a[2]), "r"(a[3]), "r"(b[0]), "r"(b[1]));
}
__device__ __forceinline__ uint32_t f2tf32(float f) {
    uint32_t u;
    asm("cvt.rna.tf32.f32 %0, %1;" : "=r"(u) : "f"(f));
    return u;
}
// exp(x) without MUFU: 2^t with t = x*log2(e), |frac| <= 0.5, degree-5 Taylor.
__device__ __forceinline__ float fast_exp(float x) {
    float t = x * 1.4426950408889634f;
    int i = __float2int_rn(t);
    float f = t - (float)i;
    float p = 1.3333558146e-3f;
    p = fmaf(p, f, 9.6181291076e-3f);
    p = fmaf(p, f, 5.5504108664e-2f);
    p = fmaf(p, f, 2.4022650696e-1f);
    p = fmaf(p, f, 6.9314718056e-1f);
    p = fmaf(p, f, 1.0f);
    float sc = __int_as_float((i + 127) << 23);
    return p * sc;
}

// ---------------- RMSNorm -> bf16 -------------------------------------------
__global__ __launch_bounds__(256) void rmsnorm_kernel(const float* __restrict__ x,
                                                      const float* __restrict__ scale) {
    int row = blockIdx.x;
    const float* xr = x + (size_t)row * H;
    float ss = 0.f;
    for (int i = threadIdx.x; i < H; i += 256) { float v = xr[i]; ss += v * v; }
    for (int o = 16; o > 0; o >>= 1) ss += __shfl_xor_sync(0xffffffffu, ss, o);
    __shared__ float red[8];
    int wid = threadIdx.x >> 5, lane = threadIdx.x & 31;
    if (lane == 0) red[wid] = ss;
    __syncthreads();
    __shared__ float s_inv;
    if (threadIdx.x == 0) {
        float t = 0.f;
        #pragma unroll
        for (int i = 0; i < 8; i++) t += red[i];
        s_inv = rsqrtf(t * (1.0f / (float)H) + 1e-5f);
    }
    __syncthreads();
    float inv = s_inv;
    for (int i = threadIdx.x; i < H; i += 256)
        g_act[(size_t)row * H + i] = __float2bfloat16(xr[i] * inv * scale[i]);
}

// ---------------- weight transpose + bf16 convert: [K,N] f32 -> [N,K] bf16 --
__global__ __launch_bounds__(256) void transpose_bf16_kernel(const float* __restrict__ S,
                                                             __nv_bfloat16* __restrict__ D,
                                                             int K, int N) {
    __shared__ float t[32][33];
    int n0 = blockIdx.x * 32, k0 = blockIdx.y * 32;
    int tx = threadIdx.x & 31, ty = threadIdx.x >> 5;
    #pragma unroll
    for (int i = 0; i < 32; i += 8)
        t[ty + i][tx] = S[(size_t)(k0 + ty + i) * N + n0 + tx];
    __syncthreads();
    #pragma unroll
    for (int i = 0; i < 32; i += 8)
        D[(size_t)(n0 + ty + i) * K + k0 + tx] = __float2bfloat16(t[tx][ty + i]);
}

// ---------------- bf16 mma.sync GEMM: C = A[M,K] @ Bt[N,K]^T + bias (+resid)
__global__ __launch_bounds__(256) void gemm_tc_kernel(const __nv_bfloat16* __restrict__ A,
                                                      const __nv_bfloat16* __restrict__ Bt,
                                                      const float* __restrict__ bias,
                                                      const float* __restrict__ resid,
                                                      float* __restrict__ C,
                                                      int N, int K) {
    extern __shared__ char smem[];
    uint32_t sbase = smem_u32(smem);

    int tid = threadIdx.x;
    int wid = tid >> 5, lane = tid & 31;
    int wm = wid & 1;
    int wn = wid >> 1;
    int bm = blockIdx.y * BM, bn = blockIdx.x * BN;

    float acc[4][4][4];
    #pragma unroll
    for (int i = 0; i < 4; i++)
        #pragma unroll
        for (int j = 0; j < 4; j++)
            #pragma unroll
            for (int e = 0; e < 4; e++) acc[i][j][e] = 0.f;

    const int nk = K / BK;

    auto load_stage = [&](int it) {
        uint32_t sb = sbase + (it & (NSTAGE - 1)) * STAGE;
        const __nv_bfloat16* Ag = A + (size_t)bm * K + it * BK;
        const __nv_bfloat16* Bg = Bt + (size_t)bn * K + it * BK;
        #pragma unroll
        for (int i = 0; i < 2; i++) {
            int c = tid + i * 256;
            int row = c >> 2, h = c & 3;
            cp_async16(sb + row * RS + h * 16, Ag + (size_t)row * K + h * 8);
        }
        #pragma unroll
        for (int i = 0; i < 2; i++) {
            int c = tid + i * 256;
            int row = c >> 2, h = c & 3;
            cp_async16(sb + STAGE_A + row * RS + h * 16, Bg + (size_t)row * K + h * 8);
        }
        asm volatile("cp.async.commit_group;" ::: "memory");
    };

    load_stage(0);
    load_stage(1);
    load_stage(2);

    uint32_t aoff = (uint32_t)(lane & 15) * RS + (uint32_t)(lane >> 4) * 16;
    uint32_t boff = (uint32_t)(wn * 32 + ((lane >> 4) << 3) + (lane & 7)) * RS
                  + (uint32_t)((lane >> 3) & 1) * 16;

    for (int it = 0; it < nk; it++) {
        asm volatile("cp.async.wait_group 2;" ::: "memory");
        __syncthreads();
        uint32_t sb = sbase + (it & (NSTAGE - 1)) * STAGE;
        uint32_t aBase = sb + (uint32_t)(wm * 64) * RS + aoff;
        uint32_t bBase = sb + STAGE_A + boff;
        #pragma unroll
        for (int ks = 0; ks < 2; ks++) {
            uint32_t a[4][4], b[2][4];
            #pragma unroll
            for (int mi = 0; mi < 4; mi++)
                ldsm4(a[mi], aBase + (uint32_t)(mi * 16) * RS + ks * 32);
            #pragma unroll
            for (int ng = 0; ng < 2; ng++)
                ldsm4(b[ng], bBase + (uint32_t)(ng * 16) * RS + ks * 32);
            #pragma unroll
            for (int mi = 0; mi < 4; mi++) {
                mma16816(acc[mi][0], a[mi], &b[0][0]);
                mma16816(acc[mi][1], a[mi], &b[0][2]);
                mma16816(acc[mi][2], a[mi], &b[1][0]);
                mma16816(acc[mi][3], a[mi], &b[1][2]);
            }
        }
        if (it + 3 < nk) load_stage(it + 3);
        else asm volatile("cp.async.commit_group;" ::: "memory");
    }

    int rq = lane >> 2, cq = (lane & 3) * 2;
    #pragma unroll
    for (int mi = 0; mi < 4; mi++) {
        int r0 = bm + wm * 64 + mi * 16 + rq;
        #pragma unroll
        for (int half = 0; half < 2; half++) {
            int r = r0 + half * 8;
            float* crow = C + (size_t)r * N;
            const float* rrow = resid ? resid + (size_t)r * N : (const float*)0;
            #pragma unroll
            for (int nj = 0; nj < 4; nj++) {
                int c = bn + wn * 32 + nj * 8 + cq;
                float2 v;
                v.x = acc[mi][nj][half * 2 + 0] + bias[c];
                v.y = acc[mi][nj][half * 2 + 1] + bias[c + 1];
                if (rrow) { v.x += rrow[c]; v.y += rrow[c + 1]; }
                *(float2*)&crow[c] = v;
            }
        }
    }
}

// ---------------- RoPE (split-half rotation), in place on g_qkv -------------
__global__ __launch_bounds__(256) void rope_kernel(const float* __restrict__ cosb,
                                                   const float* __restrict__ sinb) {
    int idx = blockIdx.x * 256 + threadIdx.x;
    if (idx >= T * 40 * 32) return;
    int i = idx & 31;
    int h = (idx >> 5) % 40;
    int t = idx / (40 * 32);
    int col = (h < 32) ? (h * HD) : (H + (h - 32) * HD);
    float* p = g_qkv + (size_t)t * QKV_N + col;
    float c = cosb[t * 32 + i], s = sinb[t * 32 + i];
    float x1 = p[i], x2 = p[i + 32];
    p[i] = x1 * c - x2 * s;
    p[i + 32] = x2 * c + x1 * s;
}

// ---------------- tensor-core windowed GQA attention with sinks -------------
// grid (T/QT, NKV), 128 threads = 4 warps; warp w = q-head (nkv*4+w), 32 queries.
// S = Q[32,64] @ K^T in tf32 mma, poly-exp softmax (fixed max 0), O = P @ V tf32.
__global__ __launch_bounds__(128, 1) void attn_tc_kernel(const float* __restrict__ sinks) {
    extern __shared__ float sh[];
    float* Qsh = sh;                          // [4][32][QSTR]
    float* Ksh = Qsh + ATT_Q_FL;              // [160][KSTR]
    float* Vsh = Ksh + ATT_K_FL;              // [160][VSTR]
    float* Psh = Vsh + ATT_V_FL;              // [4][32][PSTR]

    int nkv = blockIdx.y;
    int q0 = blockIdx.x * QT;
    int ks = q0 - SW; if (ks < 0) ks = 0;
    int nk = q0 + QT - ks;                    // always a multiple of 32
    int nchunk = nk >> 5;

    int tid = threadIdx.x, w = tid >> 5, lane = tid & 31;

    // stage Q (scaled by 1/sqrt(64))
    for (int idx = tid; idx < 32 * 64; idx += 128) {
        int row = idx >> 6, f4 = idx & 63;
        int head = f4 >> 4, c4 = (f4 & 15) << 2;
        float4 v = *(const float4*)(g_qkv + (size_t)(q0 + row) * QKV_N + (nkv * QM + head) * HD + c4);
        float* dst = Qsh + (head * 32 + row) * QSTR + c4;
        dst[0] = v.x * 0.125f; dst[1] = v.y * 0.125f;
        dst[2] = v.z * 0.125f; dst[3] = v.w * 0.125f;
    }
    // stage K, V
    const float* kbase = g_qkv + H + nkv * HD;
    const float* vbase = g_qkv + H + NKV * HD + nkv * HD;
    for (int idx = tid; idx < nk * 16; idx += 128) {
        int r0 = idx >> 4, c4 = (idx & 15) << 2;
        *(float4*)(Ksh + r0 * KSTR + c4) = *(const float4*)(kbase + (size_t)(ks + r0) * QKV_N + c4);
        *(float4*)(Vsh + r0 * VSTR + c4) = *(const float4*)(vbase + (size_t)(ks + r0) * QKV_N + c4);
    }
    __syncthreads();

    int r = lane >> 2, kq = lane & 3;

    // preload Q a-fragments (tf32): [mtile][ktile][4]
    uint32_t af[2][8][4];
    const float* Qw = Qsh + w * 32 * QSTR;
    #pragma unroll
    for (int mt = 0; mt < 2; mt++)
        #pragma unroll
        for (int kt = 0; kt < 8; kt++) {
            af[mt][kt][0] = f2tf32(Qw[(mt * 16 + r) * QSTR + kt * 8 + kq]);
            af[mt][kt][1] = f2tf32(Qw[(mt * 16 + r + 8) * QSTR + kt * 8 + kq]);
            af[mt][kt][2] = f2tf32(Qw[(mt * 16 + r) * QSTR + kt * 8 + kq + 4]);
            af[mt][kt][3] = f2tf32(Qw[(mt * 16 + r + 8) * QSTR + kt * 8 + kq + 4]);
        }

    float accO[2][8][4];
    #pragma unroll
    for (int mt = 0; mt < 2; mt++)
        #pragma unroll
        for (int nt = 0; nt < 8; nt++)
            #pragma unroll
            for (int e = 0; e < 4; e++) accO[mt][nt][e] = 0.f;
    float lsum[2][2] = {{0.f, 0.f}, {0.f, 0.f}};

    float* Pw = Psh + w * 32 * PSTR;

    for (int c = 0; c < nchunk; c++) {
        // ---- S = Q @ K^T (chunk of 32 keys) ----
        float S[2][4][4];
        #pragma unroll
        for (int mt = 0; mt < 2; mt++)
            #pragma unroll
            for (int nt = 0; nt < 4; nt++)
                #pragma unroll
                for (int e = 0; e < 4; e++) S[mt][nt][e] = 0.f;
        #pragma unroll
        for (int nt = 0; nt < 4; nt++) {
            int key = c * 32 + nt * 8 + (lane >> 2);
            #pragma unroll
            for (int kt = 0; kt < 8; kt++) {
                uint32_t b[2];
                b[0] = f2tf32(Ksh[key * KSTR + kt * 8 + kq]);
                b[1] = f2tf32(Ksh[key * KSTR + kt * 8 + kq + 4]);
                mma_tf32(S[0][nt], af[0][kt], b);
                mma_tf32(S[1][nt], af[1][kt], b);
            }
        }
        // ---- mask + exp + row-sum, P into S ----
        #pragma unroll
        for (int mt = 0; mt < 2; mt++)
            #pragma unroll
            for (int nt = 0; nt < 4; nt++)
                #pragma unroll
                for (int e = 0; e < 4; e++) {
                    int half = e >> 1;
                    int q = q0 + mt * 16 + r + half * 8;
                    int kp = ks + c * 32 + nt * 8 + 2 * kq + (e & 1);
                    float p = fast_exp(S[mt][nt][e]);
                    p = (kp <= q && q - kp <= SW) ? p : 0.f;
                    lsum[mt][half] += p;
                    S[mt][nt][e] = p;
                }
        // ---- store P to smem ----
        #pragma unroll
        for (int mt = 0; mt < 2; mt++)
            #pragma unroll
            for (int nt = 0; nt < 4; nt++) {
                *(float2*)&Pw[(mt * 16 + r) * PSTR + nt * 8 + 2 * kq] =
                    make_float2(S[mt][nt][0], S[mt][nt][1]);
                *(float2*)&Pw[(mt * 16 + r + 8) * PSTR + nt * 8 + 2 * kq] =
                    make_float2(S[mt][nt][2], S[mt][nt][3]);
            }
        __syncwarp();
        // ---- O += P @ V ----
        #pragma unroll
        for (int kt = 0; kt < 4; kt++) {
            uint32_t pa[2][4];
            #pragma unroll
            for (int mt = 0; mt < 2; mt++) {
                pa[mt][0] = f2tf32(Pw[(mt * 16 + r) * PSTR + kt * 8 + kq]);
                pa[mt][1] = f2tf32(Pw[(mt * 16 + r + 8) * PSTR + kt * 8 + kq]);
                pa[mt][2] = f2tf32(Pw[(mt * 16 + r) * PSTR + kt * 8 + kq + 4]);
                pa[mt][3] = f2tf32(Pw[(mt * 16 + r + 8) * PSTR + kt * 8 + kq + 4]);
            }
            int key = c * 32 + kt * 8;
            #pragma unroll
            for (int nt = 0; nt < 8; nt++) {
                uint32_t b[2];
                b[0] = f2tf32(Vsh[(key + kq) * VSTR + nt * 8 + (lane >> 2)]);
                b[1] = f2tf32(Vsh[(key + kq + 4) * VSTR + nt * 8 + (lane >> 2)]);
                mma_tf32(accO[0][nt], pa[0], b);
                mma_tf32(accO[1][nt], pa[1], b);
            }
        }
        __syncwarp();
    }

    // ---- finish row sums (4 lanes per row group), add sink, normalize ----
    float sk = fast_exp(sinks[nkv * QM + w]);
    float inv[2][2];
    #pragma unroll
    for (int mt = 0; mt < 2; mt++)
        #pragma unroll
        for (int half = 0; half < 2; half++) {
            float l = lsum[mt][half];
            l += __shfl_xor_sync(0xffffffffu, l, 1);
            l += __shfl_xor_sync(0xffffffffu, l, 2);
            inv[mt][half] = 1.f / (l + sk);
        }

    int headcol = (nkv * QM + w) * HD;
    #pragma unroll
    for (int mt = 0; mt < 2; mt++)
        #pragma unroll
        for (int nt = 0; nt < 8; nt++) {
            int col = headcol + nt * 8 + 2 * kq;
            int q_a = q0 + mt * 16 + r;
            int q_b = q_a + 8;
            *(__nv_bfloat162*)(g_attn + (size_t)q_a * H + col) =
                __floats2bfloat162_rn(accO[mt][nt][0] * inv[mt][0], accO[mt][nt][1] * inv[mt][0]);
            *(__nv_bfloat162*)(g_attn + (size_t)q_b * H + col) =
                __floats2bfloat162_rn(accO[mt][nt][2] * inv[mt][1], accO[mt][nt][3] * inv[mt][1]);
        }
}

// ---------------- launch -----------------------------------------------------
extern "C" void kernel_launch(void* const* d_in, const int* in_sizes, int n_in,
                              void* d_out, int out_size) {
    const float* x          = (const float*)d_in[0];
    const float* scale      = (const float*)d_in[1];
    const float* sinks      = (const float*)d_in[2];
    const float* qkv_kernel = (const float*)d_in[3];
    const float* qkv_bias   = (const float*)d_in[4];
    const float* out_kernel = (const float*)d_in[5];
    const float* out_bias   = (const float*)d_in[6];
    const float* cosb       = (const float*)d_in[7];
    const float* sinb       = (const float*)d_in[8];
    float* out = (float*)d_out;

    __nv_bfloat16 *pact, *pattn, *pqw, *pow;
    float* pq;
    cudaGetSymbolAddress((void**)&pact, g_act);
    cudaGetSymbolAddress((void**)&pq, g_qkv);
    cudaGetSymbolAddress((void**)&pattn, g_attn);
    cudaGetSymbolAddress((void**)&pqw, g_qkvw_t);
    cudaGetSymbolAddress((void**)&pow, g_outw_t);

    cudaFuncSetAttribute(attn_tc_kernel, cudaFuncAttributeMaxDynamicSharedMemorySize, ATT_SMEM);
    cudaFuncSetAttribute(gemm_tc_kernel, cudaFuncAttributeMaxDynamicSharedMemorySize, GEMM_SMEM);

    rmsnorm_kernel<<<T, 256>>>(x, scale);
    transpose_bf16_kernel<<<dim3(QKV_N / 32, H / 32), 256>>>(qkv_kernel, pqw, H, QKV_N);
    transpose_bf16_kernel<<<dim3(H / 32, H / 32), 256>>>(out_kernel, pow, H, H);
    gemm_tc_kernel<<<dim3(QKV_N / BN, T / BM), 256, GEMM_SMEM>>>(pact, pqw, qkv_bias, nullptr, pq, QKV_N, H);
    rope_kernel<<<(T * 40 * 32 + 255) / 256, 256>>>(cosb, sinb);
    attn_tc_kernel<<<dim3(T / QT, NKV), 128, ATT_SMEM>>>(sinks);
    gemm_tc_kernel<<<dim3(H / BN, T / BM), 256, GEMM_SMEM>>>(pattn, pow, out_bias, x, out, H, H);
}